// round 1
// baseline (speedup 1.0000x reference)
#include <cuda_runtime.h>
#include <cuda_bf16.h>
#include <float.h>

#define DIMS   256
#define NE     8192
#define NTOK   16384
#define TM     32
#define TN     256
#define DK     32

// Output layout (float32, concatenated in reference return order)
#define OFF_Q    0
#define OFF_DIFF 4194304
#define OFF_IND  4194305
#define OFF_OH   4210689
#define OFF_ES   4218881
#define OUT_TOT  6316033

__device__ int   g_ind[NTOK];
__device__ float g_enorm[NE];

// ---------------------------------------------------------------------------
// Zero the accumulated regions of d_out (diff, ind, onehot, embed_sum).
// quantize region is fully overwritten by scatter; ind fully overwritten too,
// so zeroing the contiguous tail [OFF_DIFF, OUT_TOT) is safe and simple.
// ---------------------------------------------------------------------------
__global__ void init_kernel(float* __restrict__ out) {
    int n = OUT_TOT - OFF_DIFF;
    for (int i = blockIdx.x * blockDim.x + threadIdx.x; i < n;
         i += gridDim.x * blockDim.x) {
        out[OFF_DIFF + i] = 0.0f;
    }
}

// ---------------------------------------------------------------------------
// Codebook squared norms: g_enorm[k] = sum_d embed[d][k]^2
// embed is [DIMS, NE] row-major -> column loads are coalesced across threads.
// ---------------------------------------------------------------------------
__global__ void norms_kernel(const float* __restrict__ embed) {
    int k = blockIdx.x * blockDim.x + threadIdx.x;
    if (k >= NE) return;
    float s = 0.0f;
#pragma unroll 8
    for (int d = 0; d < DIMS; d++) {
        float v = embed[d * NE + k];
        s += v * v;
    }
    g_enorm[k] = s;
}

// ---------------------------------------------------------------------------
// Fused GEMM + argmin.
// Block: 256 threads (8 warps), handles TM=32 tokens vs all NE codes.
// score(t,k) = ||e_k||^2 - 2 * dot(x_t, e_k); running (min,idx) in registers.
// Thread layout: warp w owns tokens [w*4, w*4+4); lane owns codes
// {lane + 32*j : j<8} within each TN=256 code tile (conflict-free LDS).
// ---------------------------------------------------------------------------
__global__ __launch_bounds__(256) void argmin_kernel(
    const float* __restrict__ x,
    const float* __restrict__ embed,
    float* __restrict__ out_ind)
{
    __shared__ float xs[DIMS][TM + 1];   // transposed x tile, padded
    __shared__ float es[DK][TN];         // embed chunk

    const int tid  = threadIdx.x;
    const int lane = tid & 31;
    const int wid  = tid >> 5;
    const int t0g  = blockIdx.x * TM;    // global token base
    const int tw0  = wid * 4;            // warp's token offset in tile

    // Load x tile [TM, DIMS] transposed into smem (float4 global reads)
    for (int idx = tid * 4; idx < TM * DIMS; idx += 256 * 4) {
        int t = idx / DIMS;
        int d = idx % DIMS;
        float4 v = *(const float4*)(x + (size_t)(t0g + t) * DIMS + d);
        xs[d + 0][t] = v.x;
        xs[d + 1][t] = v.y;
        xs[d + 2][t] = v.z;
        xs[d + 3][t] = v.w;
    }
    __syncthreads();

    float bestv[4];
    int   besti[4];
#pragma unroll
    for (int m = 0; m < 4; m++) { bestv[m] = FLT_MAX; besti[m] = 0; }

    for (int j0 = 0; j0 < NE; j0 += TN) {
        float acc[4][8];
#pragma unroll
        for (int m = 0; m < 4; m++)
#pragma unroll
            for (int j = 0; j < 8; j++) acc[m][j] = 0.0f;

        for (int kk = 0; kk < DIMS; kk += DK) {
            // load embed chunk [DK, TN] (rows contiguous in gmem, float4)
#pragma unroll
            for (int i = tid; i < DK * TN / 4; i += 256) {
                int r  = i >> 6;
                int c4 = (i & 63) * 4;
                *(float4*)&es[r][c4] =
                    *(const float4*)(embed + (size_t)(kk + r) * NE + j0 + c4);
            }
            __syncthreads();

#pragma unroll
            for (int r = 0; r < DK; r++) {
                const int d = kk + r;
                float xv0 = xs[d][tw0 + 0];
                float xv1 = xs[d][tw0 + 1];
                float xv2 = xs[d][tw0 + 2];
                float xv3 = xs[d][tw0 + 3];
#pragma unroll
                for (int j = 0; j < 8; j++) {
                    float ev = es[r][lane + 32 * j];
                    acc[0][j] += xv0 * ev;
                    acc[1][j] += xv1 * ev;
                    acc[2][j] += xv2 * ev;
                    acc[3][j] += xv3 * ev;
                }
            }
            __syncthreads();
        }

        // fold this code tile into running argmin
#pragma unroll
        for (int j = 0; j < 8; j++) {
            int c = j0 + lane + 32 * j;
            float nrm = g_enorm[c];
#pragma unroll
            for (int m = 0; m < 4; m++) {
                float s = nrm - 2.0f * acc[m][j];
                if (s < bestv[m]) { bestv[m] = s; besti[m] = c; }
            }
        }
    }

    // cross-lane (min, idx) reduction; first-index tiebreak like jnp.argmin
#pragma unroll
    for (int m = 0; m < 4; m++) {
        float v = bestv[m];
        int   ix = besti[m];
        for (int off = 16; off; off >>= 1) {
            float ov = __shfl_down_sync(0xffffffffu, v, off);
            int   oi = __shfl_down_sync(0xffffffffu, ix, off);
            if (ov < v || (ov == v && oi < ix)) { v = ov; ix = oi; }
        }
        if (lane == 0) {
            int token = t0g + tw0 + m;
            g_ind[token]   = ix;
            out_ind[token] = (float)ix;
        }
    }
}

// ---------------------------------------------------------------------------
// Epilogue: one block per token.
//   quantize_st row  = embed[:, ind]          (embed is L2-resident, 8 MB)
//   diff            += sum((q - x)^2) / (NTOK*DIMS)
//   onehot[ind]     += 1
//   embed_sum[d,ind]+= x[t,d]
// ---------------------------------------------------------------------------
__global__ __launch_bounds__(256) void scatter_kernel(
    const float* __restrict__ x,
    const float* __restrict__ embed,
    float* __restrict__ out)
{
    __shared__ float warp_sums[8];
    const int t = blockIdx.x;
    const int d = threadIdx.x;
    const int lane = d & 31;
    const int wid  = d >> 5;

    const int ind = g_ind[t];
    float xv = x[(size_t)t * DIMS + d];
    float q  = embed[(size_t)d * NE + ind];

    out[OFF_Q + (size_t)t * DIMS + d] = q;           // quantize_st == quantize
    atomicAdd(&out[OFF_ES + (size_t)d * NE + ind], xv);

    float dp = (q - xv) * (q - xv);
    // block reduce dp
    for (int off = 16; off; off >>= 1)
        dp += __shfl_down_sync(0xffffffffu, dp, off);
    if (lane == 0) warp_sums[wid] = dp;
    __syncthreads();
    if (wid == 0) {
        float s = (lane < 8) ? warp_sums[lane] : 0.0f;
        for (int off = 4; off; off >>= 1)
            s += __shfl_down_sync(0xffffffffu, s, off);
        if (lane == 0)
            atomicAdd(&out[OFF_DIFF], s * (1.0f / (float)(NTOK * DIMS)));
    }
    if (d == 0) atomicAdd(&out[OFF_OH + ind], 1.0f);
}

// ---------------------------------------------------------------------------
extern "C" void kernel_launch(void* const* d_in, const int* in_sizes, int n_in,
                              void* d_out, int out_size)
{
    const float* x     = (const float*)d_in[0];
    const float* embed = (const float*)d_in[1];
    // defensive: detect order by element counts (x=4194304, embed=2097152)
    if (n_in >= 2 && in_sizes[0] == DIMS * NE && in_sizes[1] == NTOK * DIMS) {
        const float* tmp = x; x = embed; embed = tmp;
    }
    float* out = (float*)d_out;

    init_kernel<<<2048, 512>>>(out);
    norms_kernel<<<NE / 256, 256>>>(embed);
    argmin_kernel<<<NTOK / TM, 256>>>(x, embed, out + OFF_IND);
    scatter_kernel<<<NTOK, 256>>>(x, embed, out);
}

// round 3
// speedup vs baseline: 2.5512x; 2.5512x over previous
#include <cuda_runtime.h>
#include <cuda_bf16.h>
#include <cstdint>
#include <float.h>

#define DIMS 256
#define NE   8192
#define NTOK 16384

// Output layout (float32, concatenated in reference return order)
#define OFF_Q    0
#define OFF_DIFF 4194304
#define OFF_IND  4194305
#define OFF_OH   4210689
#define OFF_ES   4218881
#define OUT_TOT  6316033

#define CAP    192
#define MARGIN 0.5f

// Phase A tiling
#define TM     128            // tokens per CTA
#define TN     128            // codes per chunk
#define NCHUNK (NE / TN)      // 64
#define ROWB   528            // padded row stride in bytes (264 bf16)

// ---------------- device scratch (static, no runtime allocs) ----------------
__device__ __nv_bfloat16 g_xbf[NTOK * DIMS];   // x bf16, K-major
__device__ __nv_bfloat16 g_ebf[NE * DIMS];     // embed^T bf16 [n][k]
__device__ float         g_ebT[NE * DIMS];     // embed^T fp32 [n][k]
__device__ float         g_enorm[NE];
__device__ int           g_ind[NTOK];
__device__ int           g_ccnt[NTOK];
__device__ float         g_cs[(size_t)NTOK * CAP];
__device__ int           g_ci[(size_t)NTOK * CAP];

// ---------------- baseline-PTX helpers (no sm_103a-only instrs) -------------
__device__ __forceinline__ uint32_t smem_u32(const void* p) {
    uint32_t a;
    asm("{ .reg .u64 t; cvta.to.shared.u64 t, %1; cvt.u32.u64 %0, t; }"
        : "=r"(a) : "l"(p));
    return a;
}
__device__ __forceinline__ void cp_async16(uint32_t dst, const void* src) {
    asm volatile("cp.async.cg.shared.global [%0], [%1], 16;"
                 :: "r"(dst), "l"(src) : "memory");
}
__device__ __forceinline__ void cp_commit() {
    asm volatile("cp.async.commit_group;" ::: "memory");
}
__device__ __forceinline__ void cp_wait0() {
    asm volatile("cp.async.wait_group 0;" ::: "memory");
}
__device__ __forceinline__ void ldsm_x4(uint32_t* r, uint32_t addr) {
    asm volatile("ldmatrix.sync.aligned.m8n8.x4.shared.b16 {%0,%1,%2,%3}, [%4];"
                 : "=r"(r[0]), "=r"(r[1]), "=r"(r[2]), "=r"(r[3]) : "r"(addr));
}
__device__ __forceinline__ void mma_bf16(float* c, const uint32_t* a,
                                         uint32_t b0, uint32_t b1) {
    asm volatile(
        "mma.sync.aligned.m16n8k16.row.col.f32.bf16.bf16.f32 "
        "{%0,%1,%2,%3}, {%4,%5,%6,%7}, {%8,%9}, {%0,%1,%2,%3};"
        : "+f"(c[0]), "+f"(c[1]), "+f"(c[2]), "+f"(c[3])
        : "r"(a[0]), "r"(a[1]), "r"(a[2]), "r"(a[3]), "r"(b0), "r"(b1));
}

// ---------------- init ------------------------------------------------------
__global__ void init_kernel(float* __restrict__ out) {
    int n = OUT_TOT - OFF_DIFF;
    for (int i = blockIdx.x * blockDim.x + threadIdx.x; i < n;
         i += gridDim.x * blockDim.x)
        out[OFF_DIFF + i] = 0.0f;
    for (int i = blockIdx.x * blockDim.x + threadIdx.x; i < NTOK;
         i += gridDim.x * blockDim.x)
        g_ccnt[i] = 0;
}

// ---------------- prep ------------------------------------------------------
__global__ void conv_x_kernel(const float* __restrict__ x) {
    int i = (blockIdx.x * blockDim.x + threadIdx.x) * 4;
    if (i >= NTOK * DIMS) return;
    float4 v = *(const float4*)(x + i);
    __nv_bfloat162 a = __floats2bfloat162_rn(v.x, v.y);
    __nv_bfloat162 b = __floats2bfloat162_rn(v.z, v.w);
    uint2 o;
    o.x = *(uint32_t*)&a;
    o.y = *(uint32_t*)&b;
    *(uint2*)(g_xbf + i) = o;
}

__global__ void transpose_kernel(const float* __restrict__ embed) {
    __shared__ float ts[32][33];
    int n0 = blockIdx.x * 32;
    int d0 = blockIdx.y * 32;
    int tx = threadIdx.x, ty = threadIdx.y;
    for (int r = ty; r < 32; r += 8)
        ts[r][tx] = embed[(size_t)(d0 + r) * NE + n0 + tx];
    __syncthreads();
    for (int r = ty; r < 32; r += 8) {
        float v = ts[tx][r];
        size_t o = (size_t)(n0 + r) * DIMS + d0 + tx;
        g_ebT[o] = v;
        g_ebf[o] = __float2bfloat16(v);
    }
}

__global__ void norms_kernel(const float* __restrict__ embed) {
    int k = blockIdx.x * blockDim.x + threadIdx.x;
    if (k >= NE) return;
    float s = 0.0f;
#pragma unroll 8
    for (int d = 0; d < DIMS; d++) {
        float v = embed[(size_t)d * NE + k];
        s += v * v;
    }
    g_enorm[k] = s;
}

// ---------------- Phase A: HMMA GEMM + candidate collection -----------------
// dyn smem: As [128*528] | Bs[2][128*528] | esm[2][128]
#define AS_OFF  0
#define BS_OFF  (TM * ROWB)                    // 67584
#define BS_SZ   (TN * ROWB)                    // 67584 per buffer
#define ES_OFF  (BS_OFF + 2 * BS_SZ)           // 202752
#define SMEM_TOT (ES_OFF + 2 * TN * 4)         // 203776

__global__ __launch_bounds__(256, 1) void phaseA_kernel() {
    extern __shared__ __align__(128) char smem[];
    const uint32_t sb = smem_u32(smem);
    const int tid  = threadIdx.x;
    const int lane = tid & 31;
    const int wid  = tid >> 5;
    const int warpM = wid & 3;            // 4 m-blocks of 32 rows
    const int warpN = wid >> 2;           // 2 n-blocks of 64 cols
    const int gid  = lane >> 2;           // fragment group id
    const int tidg = lane & 3;
    const int m0   = blockIdx.x * TM;

    // --- stage 0: A tile + B chunk 0 + esm 0 via cp.async ---
    {
        // A: 128 rows x 32 x 16B chunks
        for (int j = 0; j < 16; j++) {
            int i = tid + j * 256;
            int r = i >> 5, c = i & 31;
            cp_async16(sb + AS_OFF + r * ROWB + c * 16,
                       (const char*)g_xbf + ((size_t)(m0 + r) * DIMS + c * 16) * 0
                       + (size_t)(m0 + r) * 512 + c * 16);
        }
        // B chunk 0
        for (int j = 0; j < 16; j++) {
            int i = tid + j * 256;
            int r = i >> 5, c = i & 31;
            cp_async16(sb + BS_OFF + r * ROWB + c * 16,
                       (const char*)g_ebf + (size_t)r * 512 + c * 16);
        }
        if (tid < 32)
            cp_async16(sb + ES_OFF + tid * 16, (const char*)g_enorm + tid * 16);
        cp_commit();
    }

    // --- per-lane ldmatrix base addresses ---
    // A (m16x16 tile, mt in {0,1}): row = warpM*32 + mt*16 + ((lane>>3)&1)*8 + (lane&7)
    //                               colbyte = (lane>>4)*16
    uint32_t addrA[2];
#pragma unroll
    for (int mt = 0; mt < 2; mt++) {
        int r = warpM * 32 + mt * 16 + ((lane >> 3) & 1) * 8 + (lane & 7);
        addrA[mt] = sb + AS_OFF + r * ROWB + ((lane >> 4) * 16);
    }
    // B (two n-subtiles per ldsm, g in 0..3): row = warpN*64 + g*16 + (lane>>4)*8 + (lane&7)
    //                                         colbyte = ((lane>>3)&1)*16
    uint32_t rowoffB[4];
#pragma unroll
    for (int g = 0; g < 4; g++) {
        int r = warpN * 64 + g * 16 + (lane >> 4) * 8 + (lane & 7);
        rowoffB[g] = r * ROWB + ((lane >> 3) & 1) * 16;
    }

    float bestv[2][2];
    int   besti[2][2];
#pragma unroll
    for (int a = 0; a < 2; a++)
#pragma unroll
        for (int h = 0; h < 2; h++) { bestv[a][h] = FLT_MAX; besti[a][h] = 0; }

    const int tok0 = m0 + warpM * 32 + gid;   // +mt*16, +8 for row halves

    for (int s = 0; s < NCHUNK; s++) {
        cp_wait0();
        __syncthreads();

        if (s + 1 < NCHUNK) {
            const char* bsrc = (const char*)g_ebf + (size_t)(s + 1) * TN * 512;
            uint32_t bdst = sb + BS_OFF + ((s + 1) & 1) * BS_SZ;
#pragma unroll
            for (int j = 0; j < 16; j++) {
                int i = tid + j * 256;
                int r = i >> 5, c = i & 31;
                cp_async16(bdst + r * ROWB + c * 16, bsrc + (size_t)r * 512 + c * 16);
            }
            if (tid < 32)
                cp_async16(sb + ES_OFF + ((s + 1) & 1) * 512 + tid * 16,
                           (const char*)g_enorm + (size_t)(s + 1) * 512 + tid * 16);
            cp_commit();
        }

        const int b = s & 1;
        const uint32_t bbase = sb + BS_OFF + b * BS_SZ;

        float acc[2][8][4];
#pragma unroll
        for (int mt = 0; mt < 2; mt++)
#pragma unroll
            for (int nt = 0; nt < 8; nt++)
#pragma unroll
                for (int q = 0; q < 4; q++) acc[mt][nt][q] = 0.0f;

#pragma unroll
        for (int k = 0; k < 16; k++) {
            uint32_t afr[2][4], bfr[4][4];
            ldsm_x4(afr[0], addrA[0] + k * 32);
            ldsm_x4(afr[1], addrA[1] + k * 32);
#pragma unroll
            for (int g = 0; g < 4; g++)
                ldsm_x4(bfr[g], bbase + rowoffB[g] + k * 32);
#pragma unroll
            for (int mt = 0; mt < 2; mt++)
#pragma unroll
                for (int nt = 0; nt < 8; nt++)
                    mma_bf16(acc[mt][nt], afr[mt],
                             bfr[nt >> 1][(nt & 1) * 2],
                             bfr[nt >> 1][(nt & 1) * 2 + 1]);
        }

        // scoring + candidate collection for this chunk
        const float* esm = (const float*)(smem + ES_OFF + b * 512);
#pragma unroll
        for (int mt = 0; mt < 2; mt++) {
            const int t0 = tok0 + mt * 16;
            const int t1 = t0 + 8;
#pragma unroll
            for (int nt = 0; nt < 8; nt++) {
                const int colL = warpN * 64 + nt * 8 + tidg * 2;
                const int cg   = s * TN + colL;
                const float e0 = esm[colL];
                const float e1 = esm[colL + 1];
                float s00 = e0 - 2.0f * acc[mt][nt][0];
                float s01 = e1 - 2.0f * acc[mt][nt][1];
                float s10 = e0 - 2.0f * acc[mt][nt][2];
                float s11 = e1 - 2.0f * acc[mt][nt][3];

                if (s00 <= bestv[mt][0] + MARGIN) {
                    int pos = atomicAdd(&g_ccnt[t0], 1);
                    if (pos < CAP) { g_cs[(size_t)t0 * CAP + pos] = s00;
                                     g_ci[(size_t)t0 * CAP + pos] = cg; }
                    if (s00 < bestv[mt][0]) { bestv[mt][0] = s00; besti[mt][0] = cg; }
                }
                if (s01 <= bestv[mt][0] + MARGIN) {
                    int pos = atomicAdd(&g_ccnt[t0], 1);
                    if (pos < CAP) { g_cs[(size_t)t0 * CAP + pos] = s01;
                                     g_ci[(size_t)t0 * CAP + pos] = cg + 1; }
                    if (s01 < bestv[mt][0]) { bestv[mt][0] = s01; besti[mt][0] = cg + 1; }
                }
                if (s10 <= bestv[mt][1] + MARGIN) {
                    int pos = atomicAdd(&g_ccnt[t1], 1);
                    if (pos < CAP) { g_cs[(size_t)t1 * CAP + pos] = s10;
                                     g_ci[(size_t)t1 * CAP + pos] = cg; }
                    if (s10 < bestv[mt][1]) { bestv[mt][1] = s10; besti[mt][1] = cg; }
                }
                if (s11 <= bestv[mt][1] + MARGIN) {
                    int pos = atomicAdd(&g_ccnt[t1], 1);
                    if (pos < CAP) { g_cs[(size_t)t1 * CAP + pos] = s11;
                                     g_ci[(size_t)t1 * CAP + pos] = cg + 1; }
                    if (s11 < bestv[mt][1]) { bestv[mt][1] = s11; besti[mt][1] = cg + 1; }
                }
            }
        }
        __syncthreads();
    }
}

// ---------------- Phase C: exact fp32 rescore of candidates -----------------
__global__ __launch_bounds__(256) void phaseC_kernel(
    const float* __restrict__ x, float* __restrict__ out_ind)
{
    const int lane = threadIdx.x & 31;
    const int t = blockIdx.x * 8 + (threadIdx.x >> 5);
    if (t >= NTOK) return;

    const int n = g_ccnt[t];
    float bs = FLT_MAX;
    int bi = NE;

    if (n > CAP) {
        // overflow fallback: exhaustive exact scan
        for (int k = lane; k < NE; k += 32) {
            const float* er = g_ebT + (size_t)k * DIMS;
            const float* xr = x + (size_t)t * DIMS;
            float dot = 0.0f;
            for (int d = 0; d < DIMS; d += 4) {
                float4 xv = *(const float4*)(xr + d);
                float4 ev = *(const float4*)(er + d);
                dot += xv.x * ev.x + xv.y * ev.y + xv.z * ev.z + xv.w * ev.w;
            }
            float s = g_enorm[k] - 2.0f * dot;
            if (s < bs || (s == bs && k < bi)) { bs = s; bi = k; }
        }
        for (int off = 16; off; off >>= 1) {
            float ov = __shfl_xor_sync(0xffffffffu, bs, off);
            int oi = __shfl_xor_sync(0xffffffffu, bi, off);
            if (ov < bs || (ov == bs && oi < bi)) { bs = ov; bi = oi; }
        }
    } else {
        float am = FLT_MAX;
        for (int i = lane; i < n; i += 32)
            am = fminf(am, g_cs[(size_t)t * CAP + i]);
        for (int off = 16; off; off >>= 1)
            am = fminf(am, __shfl_xor_sync(0xffffffffu, am, off));
        const float thr = am + MARGIN;

        float xr[8];
        *(float4*)(xr)     = *(const float4*)(x + (size_t)t * DIMS + lane * 8);
        *(float4*)(xr + 4) = *(const float4*)(x + (size_t)t * DIMS + lane * 8 + 4);

        for (int i = 0; i < n; i++) {
            float s0 = g_cs[(size_t)t * CAP + i];
            if (s0 > thr) continue;
            int k = g_ci[(size_t)t * CAP + i];
            const float* er = g_ebT + (size_t)k * DIMS + lane * 8;
            float4 e0 = *(const float4*)(er);
            float4 e1 = *(const float4*)(er + 4);
            float d = xr[0] * e0.x + xr[1] * e0.y + xr[2] * e0.z + xr[3] * e0.w
                    + xr[4] * e1.x + xr[5] * e1.y + xr[6] * e1.z + xr[7] * e1.w;
            for (int off = 16; off; off >>= 1)
                d += __shfl_xor_sync(0xffffffffu, d, off);
            float s = g_enorm[k] - 2.0f * d;
            if (s < bs || (s == bs && k < bi)) { bs = s; bi = k; }
        }
    }

    if (lane == 0) {
        g_ind[t] = bi;
        out_ind[t] = (float)bi;
    }
}

// ---------------- scatter epilogue ------------------------------------------
__global__ __launch_bounds__(256) void scatter_kernel(
    const float* __restrict__ x,
    const float* __restrict__ embed,
    float* __restrict__ out)
{
    __shared__ float warp_sums[8];
    const int t = blockIdx.x;
    const int d = threadIdx.x;
    const int lane = d & 31;
    const int wid = d >> 5;

    const int ind = g_ind[t];
    float xv = x[(size_t)t * DIMS + d];
    float q = embed[(size_t)d * NE + ind];

    out[OFF_Q + (size_t)t * DIMS + d] = q;
    atomicAdd(&out[OFF_ES + (size_t)d * NE + ind], xv);

    float dp = (q - xv) * (q - xv);
    for (int off = 16; off; off >>= 1)
        dp += __shfl_down_sync(0xffffffffu, dp, off);
    if (lane == 0) warp_sums[wid] = dp;
    __syncthreads();
    if (wid == 0) {
        float s = (lane < 8) ? warp_sums[lane] : 0.0f;
        for (int off = 4; off; off >>= 1)
            s += __shfl_down_sync(0xffffffffu, s, off);
        if (lane == 0)
            atomicAdd(&out[OFF_DIFF], s * (1.0f / (float)(NTOK * DIMS)));
    }
    if (d == 0) atomicAdd(&out[OFF_OH + ind], 1.0f);
}

// ---------------------------------------------------------------------------
extern "C" void kernel_launch(void* const* d_in, const int* in_sizes, int n_in,
                              void* d_out, int out_size)
{
    const float* x = (const float*)d_in[0];
    const float* embed = (const float*)d_in[1];
    if (n_in >= 2 && in_sizes[0] == DIMS * NE && in_sizes[1] == NTOK * DIMS) {
        const float* tmp = x; x = embed; embed = tmp;
    }
    float* out = (float*)d_out;

    cudaFuncSetAttribute(phaseA_kernel,
                         cudaFuncAttributeMaxDynamicSharedMemorySize, SMEM_TOT);

    init_kernel<<<2048, 512>>>(out);
    conv_x_kernel<<<NTOK * DIMS / 4 / 256, 256>>>(x);
    transpose_kernel<<<dim3(NE / 32, DIMS / 32), dim3(32, 8)>>>(embed);
    norms_kernel<<<NE / 256, 256>>>(embed);
    phaseA_kernel<<<NTOK / TM, 256, SMEM_TOT>>>();
    phaseC_kernel<<<NTOK / 8, 256>>>(x, out + OFF_IND);
    scatter_kernel<<<NTOK, 256>>>(x, embed, out);
}